// round 15
// baseline (speedup 1.0000x reference)
#include <cuda_runtime.h>
#include <cuda_bf16.h>
#include <cuda_fp16.h>
#include <cuda_fp8.h>
#include <math.h>

#define CC 1024
#define C4 (CC/4)
#define HH 128
#define WW 128
#define HW (HH*WW)
#define NP 4096
#define NBLK (NP/8)
#define SRINV 0.125f
#define NITERS 10
#define GSCALE 16.0f
#define GSCALE_INV (1.0f/16.0f)

// ---------------- device state ----------------
__device__ __nv_bfloat16 d_img0B[HW*CC];
__device__ __nv_bfloat16 d_img1B[HW*CC];
__device__ uint4 d_ig[HW*C4];                // {img1 bf16x4, gx fp8x4, gy fp8x4}, grads pre-scaled by 16
__device__ __nv_bfloat16 d_feat0B[NP*CC];
__device__ float d_pts3d0[NP*3];
__device__ float d_bpart[2][NBLK*28];        // per-block: cost + g(6) + H-upper(21)
__device__ float d_candp2[NP*2];
__device__ float d_R[9];
__device__ float d_t[3];
__device__ float d_Rc[9];
__device__ float d_tc[3];
__device__ float d_lam;
__device__ float d_prev;
__device__ int   d_sel;
__device__ int   d_ctr;
__device__ float d_Hm[36];
__device__ float d_gv[6];

// ---------------- prep: CHW fp32 -> HWC bf16 transpose (both images via z) ----------------
__global__ void k_transpose(const float* __restrict__ src0, const float* __restrict__ src1) {
    const float* src = blockIdx.z ? src1 : src0;
    __nv_bfloat16* dst = blockIdx.z ? d_img1B : d_img0B;
    __shared__ float tile[32][33];
    int hw0 = blockIdx.x * 32;
    int c0  = blockIdx.y * 32;
#pragma unroll
    for (int i = threadIdx.y; i < 32; i += 8)
        tile[i][threadIdx.x] = src[(size_t)(c0 + i) * HW + hw0 + threadIdx.x];
    __syncthreads();
#pragma unroll
    for (int i = threadIdx.y; i < 32; i += 8)
        dst[(size_t)(hw0 + i) * CC + c0 + threadIdx.x] = __float2bfloat16(tile[threadIdx.x][i]);
}

// helpers
__device__ __forceinline__ void unpack_b4(uint2 q, float f[4]) {
    float2 a = __bfloat1622float2(*reinterpret_cast<__nv_bfloat162*>(&q.x));
    float2 b = __bfloat1622float2(*reinterpret_cast<__nv_bfloat162*>(&q.y));
    f[0] = a.x; f[1] = a.y; f[2] = b.x; f[3] = b.y;
}
__device__ __forceinline__ uint2 pack_b4(const float f[4]) {
    __nv_bfloat162 a = __floats2bfloat162_rn(f[0], f[1]);
    __nv_bfloat162 b = __floats2bfloat162_rn(f[2], f[3]);
    uint2 q;
    q.x = *reinterpret_cast<unsigned*>(&a);
    q.y = *reinterpret_cast<unsigned*>(&b);
    return q;
}
__device__ __forceinline__ unsigned pack_f8x4(const float f[4]) {
    __nv_fp8x2_storage_t lo = __nv_cvt_float2_to_fp8x2(make_float2(f[0], f[1]), __NV_SATFINITE, __NV_E4M3);
    __nv_fp8x2_storage_t hi = __nv_cvt_float2_to_fp8x2(make_float2(f[2], f[3]), __NV_SATFINITE, __NV_E4M3);
    return (unsigned)lo | ((unsigned)hi << 16);
}
__device__ __forceinline__ void unpack_f8x4_h2(unsigned q, __half2& lo, __half2& hi) {
    __half2_raw h01 = __nv_cvt_fp8x2_to_halfraw2((__nv_fp8x2_storage_t)(q & 0xFFFF), __NV_E4M3);
    __half2_raw h23 = __nv_cvt_fp8x2_to_halfraw2((__nv_fp8x2_storage_t)(q >> 16),    __NV_E4M3);
    lo = *reinterpret_cast<__half2*>(&h01);
    hi = *reinterpret_cast<__half2*>(&h23);
}

// ---------------- prep: sobel -> combined {img1, gx, gy} stream ----------------
__global__ void __launch_bounds__(256) k_sobel() {
    int x = blockIdx.x, y = blockIdx.y;
    int c = threadIdx.x;
    const uint2* img = reinterpret_cast<const uint2*>(d_img1B);
    uint2 center = img[(size_t)(y * WW + x) * C4 + c];
    float v[3][3][4];
#pragma unroll
    for (int dy = -1; dy <= 1; dy++) {
#pragma unroll
        for (int dx = -1; dx <= 1; dx++) {
            int yy = y + dy, xx = x + dx;
            float f[4] = {0.f, 0.f, 0.f, 0.f};
            if (yy >= 0 && yy < HH && xx >= 0 && xx < WW) {
                uint2 q = img[(size_t)(yy * WW + xx) * C4 + c];
                unpack_b4(q, f);
            }
#pragma unroll
            for (int j = 0; j < 4; j++) v[dy+1][dx+1][j] = f[j];
        }
    }
    float gx[4], gy[4];
#pragma unroll
    for (int j = 0; j < 4; j++) {
        gx[j] = (v[0][2][j] - v[0][0][j] + 2.f*(v[1][2][j] - v[1][0][j]) + v[2][2][j] - v[2][0][j]) * (0.125f * GSCALE);
        gy[j] = (v[2][0][j] - v[0][0][j] + 2.f*(v[2][1][j] - v[0][1][j]) + v[2][2][j] - v[0][2][j]) * (0.125f * GSCALE);
    }
    uint4 o;
    o.x = center.x;
    o.y = center.y;
    o.z = pack_f8x4(gx);
    o.w = pack_f8x4(gy);
    d_ig[(size_t)(y * WW + x) * C4 + c] = o;
}

// ---------------- bilinear setup ----------------
struct BilinSetup {
    int b00, b10, b01, b11;
    float w00, w10, w01, w11;
};
__device__ __forceinline__ BilinSetup bilin_setup(float x, float y) {
    BilinSetup s;
    float x0f = floorf(x), y0f = floorf(y);
    float wx = x - x0f, wy = y - y0f;
    int x0 = min(max((int)x0f, 0), WW-1);
    int x1 = min(max(x0 + 1, 0), WW-1);
    int y0 = min(max((int)y0f, 0), HH-1);
    int y1 = min(max(y0 + 1, 0), HH-1);
    s.w00 = (1.f-wx)*(1.f-wy); s.w10 = wx*(1.f-wy);
    s.w01 = (1.f-wx)*wy;       s.w11 = wx*wy;
    s.b00 = (y0*WW + x0); s.b10 = (y0*WW + x1);
    s.b01 = (y1*WW + x0); s.b11 = (y1*WW + x1);
    return s;
}
__device__ __forceinline__ float bil(float a, float b, float c, float d, const BilinSetup& s) {
    return a*s.w00 + b*s.w10 + c*s.w01 + d*s.w11;
}

// ---- branch-free 4x4 inverse via adjugate (fp32) ----
__device__ __forceinline__ void inv4x4_adj(const float m[16], float inv[16]) {
    float s0 = m[0]*m[5] - m[4]*m[1];
    float s1 = m[0]*m[6] - m[4]*m[2];
    float s2 = m[0]*m[7] - m[4]*m[3];
    float s3 = m[1]*m[6] - m[5]*m[2];
    float s4 = m[1]*m[7] - m[5]*m[3];
    float s5 = m[2]*m[7] - m[6]*m[3];
    float c5 = m[10]*m[15] - m[14]*m[11];
    float c4 = m[9]*m[15]  - m[13]*m[11];
    float c3 = m[9]*m[14]  - m[13]*m[10];
    float c2 = m[8]*m[15]  - m[12]*m[11];
    float c1 = m[8]*m[14]  - m[12]*m[10];
    float c0 = m[8]*m[13]  - m[12]*m[9];
    float det = s0*c5 - s1*c4 + s2*c3 + s3*c2 - s4*c1 + s5*c0;
    float id = 1.0f / det;
    inv[0]  = ( m[5]*c5 - m[6]*c4 + m[7]*c3) * id;
    inv[1]  = (-m[1]*c5 + m[2]*c4 - m[3]*c3) * id;
    inv[2]  = ( m[13]*s5 - m[14]*s4 + m[15]*s3) * id;
    inv[3]  = (-m[9]*s5  + m[10]*s4 - m[11]*s3) * id;
    inv[4]  = (-m[4]*c5 + m[6]*c2 - m[7]*c1) * id;
    inv[5]  = ( m[0]*c5 - m[2]*c2 + m[3]*c1) * id;
    inv[6]  = (-m[12]*s5 + m[14]*s2 - m[15]*s1) * id;
    inv[7]  = ( m[8]*s5  - m[10]*s2 + m[11]*s1) * id;
    inv[8]  = ( m[4]*c4 - m[5]*c2 + m[7]*c0) * id;
    inv[9]  = (-m[0]*c4 + m[1]*c2 - m[3]*c0) * id;
    inv[10] = ( m[12]*s4 - m[13]*s2 + m[15]*s0) * id;
    inv[11] = (-m[8]*s4  + m[9]*s2  - m[11]*s0) * id;
    inv[12] = (-m[4]*c3 + m[5]*c1 - m[6]*c0) * id;
    inv[13] = ( m[0]*c3 - m[1]*c1 + m[2]*c0) * id;
    inv[14] = (-m[12]*s3 + m[13]*s1 - m[14]*s0) * id;
    inv[15] = ( m[8]*s3  - m[9]*s1  + m[10]*s0) * id;
}

// ---------------- prep: feat0 (warp/point, pipelined) + pts3d0 + init state ----------------
__global__ void __launch_bounds__(256) k_feat0(const float* __restrict__ pts2d,
                                               const float* __restrict__ p3d,
                                               const float* __restrict__ rm,
                                               const float* __restrict__ qm) {
    int warp = threadIdx.x >> 5;
    int lane = threadIdx.x & 31;
    int n = blockIdx.x * 8 + warp;

    if (lane == 0) {
        float X = p3d[3*n], Y = p3d[3*n+1], Z = p3d[3*n+2];
        float px = rm[0]*X + rm[1]*Y + rm[2]*Z + rm[3];
        float py = rm[4]*X + rm[5]*Y + rm[6]*Z + rm[7];
        float pz = rm[8]*X + rm[9]*Y + rm[10]*Z + rm[11];
        float pw = rm[12]*X + rm[13]*Y + rm[14]*Z + rm[15];
        d_pts3d0[3*n]   = px / pw;
        d_pts3d0[3*n+1] = py / pw;
        d_pts3d0[3*n+2] = pz / pw;
    }
    if (blockIdx.x == 0 && threadIdx.x == 0) {
        float M[16], Minv[16];
#pragma unroll
        for (int i = 0; i < 16; i++) M[i] = rm[i];
        inv4x4_adj(M, Minv);
#pragma unroll
        for (int i = 0; i < 3; i++) {
#pragma unroll
            for (int j = 0; j < 4; j++) {
                float s = 0.f;
#pragma unroll
                for (int k = 0; k < 4; k++) s += qm[i*4+k] * Minv[k*4+j];
                if (j < 3) { d_R[i*3+j] = s; d_Rc[i*3+j] = s; }
                else       { d_t[i] = s; d_tc[i] = s; }
            }
        }
        d_lam = 0.01f;
        d_sel = 0;
        d_ctr = 0;
    }

    BilinSetup s = bilin_setup(pts2d[2*n] * SRINV, pts2d[2*n+1] * SRINV);
    const uint2* img = reinterpret_cast<const uint2*>(d_img0B);
    uint2* dst = reinterpret_cast<uint2*>(d_feat0B) + (size_t)n * C4;

    uint2 a00 = img[(size_t)s.b00*C4 + lane];
    uint2 a10 = img[(size_t)s.b10*C4 + lane];
    uint2 a01 = img[(size_t)s.b01*C4 + lane];
    uint2 a11 = img[(size_t)s.b11*C4 + lane];
#pragma unroll
    for (int j = 0; j < 8; j++) {
        uint2 n00, n10, n01, n11;
        if (j < 7) {
            int c = lane + 32*(j+1);
            n00 = img[(size_t)s.b00*C4 + c];
            n10 = img[(size_t)s.b10*C4 + c];
            n01 = img[(size_t)s.b01*C4 + c];
            n11 = img[(size_t)s.b11*C4 + c];
        }
        float f00[4], f10[4], f01[4], f11[4], o[4];
        unpack_b4(a00, f00); unpack_b4(a10, f10);
        unpack_b4(a01, f01); unpack_b4(a11, f11);
#pragma unroll
        for (int k = 0; k < 4; k++)
            o[k] = bil(f00[k], f10[k], f01[k], f11[k], s);
        dst[lane + 32*j] = pack_b4(o);
        if (j < 7) { a00 = n00; a10 = n10; a01 = n01; a11 = n11; }
    }
}

// ---------------- projection helper ----------------
__device__ __forceinline__ void project_pt(int n, const float* R, const float* t,
                                           const float* __restrict__ Km,
                                           float& px, float& py, float& pz,
                                           float& p2x, float& p2y) {
    float X = d_pts3d0[3*n], Y = d_pts3d0[3*n+1], Z = d_pts3d0[3*n+2];
    px = R[0]*X + R[1]*Y + R[2]*Z + t[0];
    py = R[3]*X + R[4]*Y + R[5]*Z + t[1];
    pz = R[6]*X + R[7]*Y + R[8]*Z + t[2];
    float qx = Km[0]*px + Km[1]*py + Km[2]*pz;
    float qy = Km[3]*px + Km[4]*py + Km[5]*pz;
    float qz = Km[6]*px + Km[7]*py + Km[8]*pz;
    p2x = qx / qz; p2y = qy / qz;
}

// ---------------- FUSED: cost+jac gather + LAST-BLOCK update epilogue ----------------
__global__ void __launch_bounds__(256) k_iter(int mode, const float* __restrict__ Km,
                                              float* __restrict__ out) {
    int tid  = threadIdx.x;
    int warp = tid >> 5;
    int lane = tid & 31;
    int n = blockIdx.x * 8 + warp;
    int cand = d_sel ^ 1;    // read by ALL blocks before any tail runs (counter ordering)
    {
        float R[9], t[3];
#pragma unroll
        for (int i = 0; i < 9; i++) R[i] = d_Rc[i];
#pragma unroll
        for (int i = 0; i < 3; i++) t[i] = d_tc[i];
        float px, py, pz, p2x, p2y;
        project_pt(n, R, t, Km, px, py, pz, p2x, p2y);
        float ix = fminf(fmaxf(p2x * SRINV, 0.f), (float)(WW-1));
        float iy = fminf(fmaxf(p2y * SRINV, 0.f), (float)(HH-1));
        BilinSetup s = bilin_setup(ix, iy);
        __half2 hw00 = __float2half2_rn(s.w00 * GSCALE_INV);
        __half2 hw10 = __float2half2_rn(s.w10 * GSCALE_INV);
        __half2 hw01 = __float2half2_rn(s.w01 * GSCALE_INV);
        __half2 hw11 = __float2half2_rn(s.w11 * GSCALE_INV);

        const uint4* IG = d_ig;
        const uint2* F0 = reinterpret_cast<const uint2*>(d_feat0B) + (size_t)n * C4;

        float cst = 0.f, sx = 0.f, sy = 0.f, sxx = 0.f, sxy = 0.f, syy = 0.f;

        uint4 a00 = IG[(size_t)s.b00*C4 + lane];
        uint4 a10 = IG[(size_t)s.b10*C4 + lane];
        uint4 a01 = IG[(size_t)s.b01*C4 + lane];
        uint4 a11 = IG[(size_t)s.b11*C4 + lane];
        uint2 af0 = F0[lane];
#pragma unroll
        for (int j = 0; j < 8; j++) {
            uint4 n00, n10, n01, n11; uint2 nf0;
            if (j < 7) {
                int c = lane + 32*(j+1);
                n00 = IG[(size_t)s.b00*C4 + c];
                n10 = IG[(size_t)s.b10*C4 + c];
                n01 = IG[(size_t)s.b01*C4 + c];
                n11 = IG[(size_t)s.b11*C4 + c];
                nf0 = F0[c];
            }

            float i0v[4], i1v[4], i2v[4], i3v[4], f0v[4];
            unpack_b4(make_uint2(a00.x, a00.y), i0v);
            unpack_b4(make_uint2(a10.x, a10.y), i1v);
            unpack_b4(make_uint2(a01.x, a01.y), i2v);
            unpack_b4(make_uint2(a11.x, a11.y), i3v);
            unpack_b4(af0, f0v);

            __half2 gx00l, gx00h, gy00l, gy00h;
            __half2 gx10l, gx10h, gy10l, gy10h;
            __half2 gx01l, gx01h, gy01l, gy01h;
            __half2 gx11l, gx11h, gy11l, gy11h;
            unpack_f8x4_h2(a00.z, gx00l, gx00h); unpack_f8x4_h2(a00.w, gy00l, gy00h);
            unpack_f8x4_h2(a10.z, gx10l, gx10h); unpack_f8x4_h2(a10.w, gy10l, gy10h);
            unpack_f8x4_h2(a01.z, gx01l, gx01h); unpack_f8x4_h2(a01.w, gy01l, gy01h);
            unpack_f8x4_h2(a11.z, gx11l, gx11h); unpack_f8x4_h2(a11.w, gy11l, gy11h);

            __half2 jxl = __hfma2(gx11l, hw11, __hfma2(gx01l, hw01, __hfma2(gx10l, hw10, __hmul2(gx00l, hw00))));
            __half2 jxh = __hfma2(gx11h, hw11, __hfma2(gx01h, hw01, __hfma2(gx10h, hw10, __hmul2(gx00h, hw00))));
            __half2 jyl = __hfma2(gy11l, hw11, __hfma2(gy01l, hw01, __hfma2(gy10l, hw10, __hmul2(gy00l, hw00))));
            __half2 jyh = __hfma2(gy11h, hw11, __hfma2(gy01h, hw01, __hfma2(gy10h, hw10, __hmul2(gy00h, hw00))));
            float2 jxlf = __half22float2(jxl), jxhf = __half22float2(jxh);
            float2 jylf = __half22float2(jyl), jyhf = __half22float2(jyh);
            float jxv[4] = { jxlf.x, jxlf.y, jxhf.x, jxhf.y };
            float jyv[4] = { jylf.x, jylf.y, jyhf.x, jyhf.y };

#pragma unroll
            for (int k = 0; k < 4; k++) {
                float f1 = bil(i0v[k], i1v[k], i2v[k], i3v[k], s);
                float e  = f1 - f0v[k];
                float jx = jxv[k], jy = jyv[k];
                cst += e*e;
                sx += jx*e; sy += jy*e;
                sxx += jx*jx; sxy += jx*jy; syy += jy*jy;
            }
            if (j < 7) { a00 = n00; a10 = n10; a01 = n01; a11 = n11; af0 = nf0; }
        }

#pragma unroll
        for (int off = 16; off; off >>= 1) {
            cst += __shfl_down_sync(0xffffffffu, cst, off);
            sx  += __shfl_down_sync(0xffffffffu, sx,  off);
            sy  += __shfl_down_sync(0xffffffffu, sy,  off);
            sxx += __shfl_down_sync(0xffffffffu, sxx, off);
            sxy += __shfl_down_sync(0xffffffffu, sxy, off);
            syy += __shfl_down_sync(0xffffffffu, syy, off);
        }

        __shared__ float sblk[8][28];
        if (lane == 0) {
            d_candp2[2*n]   = p2x;
            d_candp2[2*n+1] = p2y;

            float fx = Km[0], fy = Km[4];
            float invz = 1.f / pz;
            float sc = invz * SRINV;
            float a00f = fx * sc, a02f = -fx * px * invz * sc;
            float a11f = fy * sc, a12f = -fy * py * invz * sc;
            float A0[6], A1[6];
            A0[0] = a00f; A0[1] = 0.f; A0[2] = a02f;
            A1[0] = 0.f; A1[1] = a11f; A1[2] = a12f;
            A0[3] = a02f*py;
            A0[4] = a00f*pz - a02f*px;
            A0[5] = -a00f*py;
            A1[3] = -(a11f*pz - a12f*py);
            A1[4] = a12f*px;
            A1[5] = a11f*px;

            sblk[warp][0] = cst;
#pragma unroll
            for (int k = 0; k < 6; k++)
                sblk[warp][1+k] = sx*A0[k] + sy*A1[k];
            int idx = 7;
#pragma unroll
            for (int k = 0; k < 6; k++)
#pragma unroll
                for (int l = k; l < 6; l++) {
                    sblk[warp][idx] = sxx*A0[k]*A0[l] + sxy*(A0[k]*A1[l] + A1[k]*A0[l]) + syy*A1[k]*A1[l];
                    idx++;
                }
        }
        __syncthreads();
        if (tid < 28) {
            float v = 0.f;
#pragma unroll
            for (int w = 0; w < 8; w++) v += sblk[w][tid];
            d_bpart[cand][blockIdx.x*28 + tid] = v;
        }
    }

    // ---- tail-block detection (lightweight) ----
    __shared__ int s_last;
    __threadfence();                 // order this thread's global writes
    __syncthreads();                 // all threads' writes issued + fenced
    if (tid == 0) {
        int v = atomicAdd(&d_ctr, 1);
        s_last = (v == NBLK - 1) ? 1 : 0;
    }
    __syncthreads();
    if (!s_last) return;
    __threadfence();                 // acquire side

    // =========== TAIL: reduce 512x28 + accept + copy + solve ===========
    const float* B = d_bpart[cand];
    __shared__ float sred[28][8];
    __shared__ float tot[28];
    if (tid < 224) {
        int comp = tid >> 3, part = tid & 7;
        float v = 0.f;
        int base = part * 64;
        for (int b = 0; b < 64; b++) v += B[(base + b)*28 + comp];
        sred[comp][part] = v;
    }
    __syncthreads();
    if (tid < 28) {
        float v = 0.f;
#pragma unroll
        for (int p = 0; p < 8; p++) v += sred[tid][p];
        tot[tid] = v;
    }
    __syncthreads();

    __shared__ int s_acc;
    if (tid == 0) {
        d_ctr = 0;
        float newc = tot[0] / (float)NP;
        int a;
        if (mode == 0) {
            d_prev = newc;
            d_sel = 1;
            a = 1;
        } else {
            a = (newc <= d_prev) ? 1 : 0;
            if (a) {
#pragma unroll
                for (int i = 0; i < 9; i++) d_R[i] = d_Rc[i];
#pragma unroll
                for (int i = 0; i < 3; i++) d_t[i] = d_tc[i];
                d_prev = newc;
                d_sel ^= 1;
            }
            float l = d_lam * (a ? 0.1f : 10.f);
            d_lam = fminf(fmaxf(l, 1e-6f), 100.f);
        }
        if (a) {
#pragma unroll
            for (int k = 0; k < 6; k++) d_gv[k] = tot[1+k];
            int idx = 7;
            for (int k = 0; k < 6; k++)
                for (int l = k; l < 6; l++) {
                    d_Hm[k*6+l] = tot[idx];
                    d_Hm[l*6+k] = tot[idx];
                    idx++;
                }
        }
        s_acc = a;
    }
    __syncthreads();
    if (s_acc) {
        const float2* src = reinterpret_cast<const float2*>(d_candp2);
        float2* dst = reinterpret_cast<float2*>(out);
        for (int m = tid; m < NP; m += 256) dst[m] = src[m];
    }
    if (tid != 0) return;

    // ---- fp32 LM solve (single thread) ----
    float Hd[6][7];
    float lam = d_lam;
    for (int k = 0; k < 6; k++) {
        for (int l = 0; l < 6; l++) Hd[k][l] = d_Hm[k*6+l];
        Hd[k][k] += (d_Hm[k*6+k] + 1e-9f) * lam;
        Hd[k][6] = -d_gv[k];
    }
    for (int col = 0; col < 6; col++) {
        int piv = col; float best = fabsf(Hd[col][col]);
        for (int r = col+1; r < 6; r++) if (fabsf(Hd[r][col]) > best) { best = fabsf(Hd[r][col]); piv = r; }
        if (piv != col) for (int j = 0; j < 7; j++) { float tmp = Hd[col][j]; Hd[col][j] = Hd[piv][j]; Hd[piv][j] = tmp; }
        float ip = 1.0f / Hd[col][col];
        for (int r = col+1; r < 6; r++) {
            float f = Hd[r][col] * ip;
            for (int j = col; j < 7; j++) Hd[r][j] -= f * Hd[col][j];
        }
    }
    float delta[6];
    for (int r = 5; r >= 0; r--) {
        float sv = Hd[r][6];
        for (int j = r+1; j < 6; j++) sv -= Hd[r][j] * delta[j];
        delta[r] = sv / Hd[r][r];
    }
    float w0 = delta[3], w1 = delta[4], w2 = delta[5];
    float th2 = w0*w0 + w1*w1 + w2*w2;
    float th = sqrtf(fmaxf(th2, 1e-24f));
    float Ac = (th2 < 1e-16f) ? 1.0f : sinf(th) / th;
    float Bc = (th2 < 1e-16f) ? 0.5f : (1.0f - cosf(th)) / fmaxf(th2, 1e-24f);
    float dr[3][3];
    dr[0][0] = 1.0f + Bc*(w0*w0 - th2);
    dr[0][1] = -Ac*w2 + Bc*w0*w1;
    dr[0][2] =  Ac*w1 + Bc*w0*w2;
    dr[1][0] =  Ac*w2 + Bc*w1*w0;
    dr[1][1] = 1.0f + Bc*(w1*w1 - th2);
    dr[1][2] = -Ac*w0 + Bc*w1*w2;
    dr[2][0] = -Ac*w1 + Bc*w2*w0;
    dr[2][1] =  Ac*w0 + Bc*w2*w1;
    dr[2][2] = 1.0f + Bc*(w2*w2 - th2);
    for (int i = 0; i < 3; i++) {
        for (int j = 0; j < 3; j++) {
            float sv = 0.0f;
            for (int k = 0; k < 3; k++) sv += dr[i][k] * d_R[k*3+j];
            d_Rc[i*3+j] = sv;
        }
        float sv = delta[i];
        for (int k = 0; k < 3; k++) sv += dr[i][k] * d_t[k];
        d_tc[i] = sv;
    }
}

// ---------------- launch ----------------
extern "C" void kernel_launch(void* const* d_in, const int* in_sizes, int n_in,
                              void* d_out, int out_size) {
    const float* imgf0 = (const float*)d_in[0];
    const float* imgf1 = (const float*)d_in[1];
    const float* pts2d = (const float*)d_in[2];
    const float* pts3d = (const float*)d_in[3];
    const float* qm    = (const float*)d_in[4];
    const float* rm    = (const float*)d_in[5];
    const float* Km    = (const float*)d_in[6];
    float* out = (float*)d_out;

    dim3 tb(32, 8);
    k_transpose<<<dim3(HW/32, CC/32, 2), tb>>>(imgf0, imgf1);
    k_sobel<<<dim3(WW, HH), 256>>>();
    k_feat0<<<NP/8, 256>>>(pts2d, pts3d, rm, qm);

    k_iter<<<NBLK, 256>>>(0, Km, out);
    for (int it = 0; it < NITERS; it++)
        k_iter<<<NBLK, 256>>>(1, Km, out);
}

// round 16
// speedup vs baseline: 1.2949x; 1.2949x over previous
#include <cuda_runtime.h>
#include <cuda_bf16.h>
#include <cuda_fp16.h>
#include <cuda_fp8.h>
#include <math.h>

#define CC 1024
#define C4 (CC/4)
#define HH 128
#define WW 128
#define HW (HH*WW)
#define NP 4096
#define NBLK (NP/8)
#define SRINV 0.125f
#define NITERS 10
#define GSCALE 16.0f
#define GSCALE_INV (1.0f/16.0f)

// ---------------- device state ----------------
__device__ __nv_bfloat16 d_img0B[HW*CC];
__device__ __nv_bfloat16 d_img1B[HW*CC];
__device__ uint4 d_ig[HW*C4];                // {img1 bf16x4, gx fp8x4, gy fp8x4}, grads pre-scaled by 16
__device__ __nv_bfloat16 d_feat0B[NP*CC];
__device__ float d_pts3d0[NP*3];
__device__ float d_bpart[2][NBLK*28];        // per-block: cost + g(6) + H-upper(21)
__device__ float d_candp2[NP*2];
__device__ float d_R[9];
__device__ float d_t[3];
__device__ float d_Rc[9];
__device__ float d_tc[3];
__device__ float d_lam;
__device__ float d_prev;
__device__ int   d_sel;
__device__ float d_Hm[36];
__device__ float d_gv[6];

// ---------------- prep: CHW fp32 -> HWC bf16 transpose (both images via z) ----------------
__global__ void k_transpose(const float* __restrict__ src0, const float* __restrict__ src1) {
    const float* src = blockIdx.z ? src1 : src0;
    __nv_bfloat16* dst = blockIdx.z ? d_img1B : d_img0B;
    __shared__ float tile[32][33];
    int hw0 = blockIdx.x * 32;
    int c0  = blockIdx.y * 32;
#pragma unroll
    for (int i = threadIdx.y; i < 32; i += 8)
        tile[i][threadIdx.x] = src[(size_t)(c0 + i) * HW + hw0 + threadIdx.x];
    __syncthreads();
#pragma unroll
    for (int i = threadIdx.y; i < 32; i += 8)
        dst[(size_t)(hw0 + i) * CC + c0 + threadIdx.x] = __float2bfloat16(tile[threadIdx.x][i]);
}

// helpers
__device__ __forceinline__ void unpack_b4(uint2 q, float f[4]) {
    float2 a = __bfloat1622float2(*reinterpret_cast<__nv_bfloat162*>(&q.x));
    float2 b = __bfloat1622float2(*reinterpret_cast<__nv_bfloat162*>(&q.y));
    f[0] = a.x; f[1] = a.y; f[2] = b.x; f[3] = b.y;
}
__device__ __forceinline__ uint2 pack_b4(const float f[4]) {
    __nv_bfloat162 a = __floats2bfloat162_rn(f[0], f[1]);
    __nv_bfloat162 b = __floats2bfloat162_rn(f[2], f[3]);
    uint2 q;
    q.x = *reinterpret_cast<unsigned*>(&a);
    q.y = *reinterpret_cast<unsigned*>(&b);
    return q;
}
__device__ __forceinline__ unsigned pack_f8x4(const float f[4]) {
    __nv_fp8x2_storage_t lo = __nv_cvt_float2_to_fp8x2(make_float2(f[0], f[1]), __NV_SATFINITE, __NV_E4M3);
    __nv_fp8x2_storage_t hi = __nv_cvt_float2_to_fp8x2(make_float2(f[2], f[3]), __NV_SATFINITE, __NV_E4M3);
    return (unsigned)lo | ((unsigned)hi << 16);
}
__device__ __forceinline__ void unpack_f8x4_h2(unsigned q, __half2& lo, __half2& hi) {
    __half2_raw h01 = __nv_cvt_fp8x2_to_halfraw2((__nv_fp8x2_storage_t)(q & 0xFFFF), __NV_E4M3);
    __half2_raw h23 = __nv_cvt_fp8x2_to_halfraw2((__nv_fp8x2_storage_t)(q >> 16),    __NV_E4M3);
    lo = *reinterpret_cast<__half2*>(&h01);
    hi = *reinterpret_cast<__half2*>(&h23);
}
__device__ __forceinline__ __nv_bfloat162 as_bf2(unsigned& u) {
    return *reinterpret_cast<__nv_bfloat162*>(&u);
}

// ---------------- prep: sobel -> combined {img1, gx, gy} stream ----------------
__global__ void __launch_bounds__(256) k_sobel() {
    int x = blockIdx.x, y = blockIdx.y;
    int c = threadIdx.x;
    const uint2* img = reinterpret_cast<const uint2*>(d_img1B);
    uint2 center = img[(size_t)(y * WW + x) * C4 + c];
    float v[3][3][4];
#pragma unroll
    for (int dy = -1; dy <= 1; dy++) {
#pragma unroll
        for (int dx = -1; dx <= 1; dx++) {
            int yy = y + dy, xx = x + dx;
            float f[4] = {0.f, 0.f, 0.f, 0.f};
            if (yy >= 0 && yy < HH && xx >= 0 && xx < WW) {
                uint2 q = img[(size_t)(yy * WW + xx) * C4 + c];
                unpack_b4(q, f);
            }
#pragma unroll
            for (int j = 0; j < 4; j++) v[dy+1][dx+1][j] = f[j];
        }
    }
    float gx[4], gy[4];
#pragma unroll
    for (int j = 0; j < 4; j++) {
        gx[j] = (v[0][2][j] - v[0][0][j] + 2.f*(v[1][2][j] - v[1][0][j]) + v[2][2][j] - v[2][0][j]) * (0.125f * GSCALE);
        gy[j] = (v[2][0][j] - v[0][0][j] + 2.f*(v[2][1][j] - v[0][1][j]) + v[2][2][j] - v[0][2][j]) * (0.125f * GSCALE);
    }
    uint4 o;
    o.x = center.x;
    o.y = center.y;
    o.z = pack_f8x4(gx);
    o.w = pack_f8x4(gy);
    d_ig[(size_t)(y * WW + x) * C4 + c] = o;
}

// ---------------- bilinear setup ----------------
struct BilinSetup {
    int b00, b10, b01, b11;
    float w00, w10, w01, w11;
};
__device__ __forceinline__ BilinSetup bilin_setup(float x, float y) {
    BilinSetup s;
    float x0f = floorf(x), y0f = floorf(y);
    float wx = x - x0f, wy = y - y0f;
    int x0 = min(max((int)x0f, 0), WW-1);
    int x1 = min(max(x0 + 1, 0), WW-1);
    int y0 = min(max((int)y0f, 0), HH-1);
    int y1 = min(max(y0 + 1, 0), HH-1);
    s.w00 = (1.f-wx)*(1.f-wy); s.w10 = wx*(1.f-wy);
    s.w01 = (1.f-wx)*wy;       s.w11 = wx*wy;
    s.b00 = (y0*WW + x0); s.b10 = (y0*WW + x1);
    s.b01 = (y1*WW + x0); s.b11 = (y1*WW + x1);
    return s;
}
__device__ __forceinline__ float bil(float a, float b, float c, float d, const BilinSetup& s) {
    return a*s.w00 + b*s.w10 + c*s.w01 + d*s.w11;
}

// ---- branch-free 4x4 inverse via adjugate (fp32) ----
__device__ __forceinline__ void inv4x4_adj(const float m[16], float inv[16]) {
    float s0 = m[0]*m[5] - m[4]*m[1];
    float s1 = m[0]*m[6] - m[4]*m[2];
    float s2 = m[0]*m[7] - m[4]*m[3];
    float s3 = m[1]*m[6] - m[5]*m[2];
    float s4 = m[1]*m[7] - m[5]*m[3];
    float s5 = m[2]*m[7] - m[6]*m[3];
    float c5 = m[10]*m[15] - m[14]*m[11];
    float c4 = m[9]*m[15]  - m[13]*m[11];
    float c3 = m[9]*m[14]  - m[13]*m[10];
    float c2 = m[8]*m[15]  - m[12]*m[11];
    float c1 = m[8]*m[14]  - m[12]*m[10];
    float c0 = m[8]*m[13]  - m[12]*m[9];
    float det = s0*c5 - s1*c4 + s2*c3 + s3*c2 - s4*c1 + s5*c0;
    float id = 1.0f / det;
    inv[0]  = ( m[5]*c5 - m[6]*c4 + m[7]*c3) * id;
    inv[1]  = (-m[1]*c5 + m[2]*c4 - m[3]*c3) * id;
    inv[2]  = ( m[13]*s5 - m[14]*s4 + m[15]*s3) * id;
    inv[3]  = (-m[9]*s5  + m[10]*s4 - m[11]*s3) * id;
    inv[4]  = (-m[4]*c5 + m[6]*c2 - m[7]*c1) * id;
    inv[5]  = ( m[0]*c5 - m[2]*c2 + m[3]*c1) * id;
    inv[6]  = (-m[12]*s5 + m[14]*s2 - m[15]*s1) * id;
    inv[7]  = ( m[8]*s5  - m[10]*s2 + m[11]*s1) * id;
    inv[8]  = ( m[4]*c4 - m[5]*c2 + m[7]*c0) * id;
    inv[9]  = (-m[0]*c4 + m[1]*c2 - m[3]*c0) * id;
    inv[10] = ( m[12]*s4 - m[13]*s2 + m[15]*s0) * id;
    inv[11] = (-m[8]*s4  + m[9]*s2  - m[11]*s0) * id;
    inv[12] = (-m[4]*c3 + m[5]*c1 - m[6]*c0) * id;
    inv[13] = ( m[0]*c3 - m[1]*c1 + m[2]*c0) * id;
    inv[14] = (-m[12]*s3 + m[13]*s1 - m[14]*s0) * id;
    inv[15] = ( m[8]*s3  - m[9]*s1  + m[10]*s0) * id;
}

// ---------------- prep: feat0 (warp/point, pipelined) + pts3d0 + init state ----------------
__global__ void __launch_bounds__(256) k_feat0(const float* __restrict__ pts2d,
                                               const float* __restrict__ p3d,
                                               const float* __restrict__ rm,
                                               const float* __restrict__ qm) {
    int warp = threadIdx.x >> 5;
    int lane = threadIdx.x & 31;
    int n = blockIdx.x * 8 + warp;

    if (lane == 0) {
        float X = p3d[3*n], Y = p3d[3*n+1], Z = p3d[3*n+2];
        float px = rm[0]*X + rm[1]*Y + rm[2]*Z + rm[3];
        float py = rm[4]*X + rm[5]*Y + rm[6]*Z + rm[7];
        float pz = rm[8]*X + rm[9]*Y + rm[10]*Z + rm[11];
        float pw = rm[12]*X + rm[13]*Y + rm[14]*Z + rm[15];
        d_pts3d0[3*n]   = px / pw;
        d_pts3d0[3*n+1] = py / pw;
        d_pts3d0[3*n+2] = pz / pw;
    }
    if (blockIdx.x == 0 && threadIdx.x == 0) {
        float M[16], Minv[16];
#pragma unroll
        for (int i = 0; i < 16; i++) M[i] = rm[i];
        inv4x4_adj(M, Minv);
#pragma unroll
        for (int i = 0; i < 3; i++) {
#pragma unroll
            for (int j = 0; j < 4; j++) {
                float s = 0.f;
#pragma unroll
                for (int k = 0; k < 4; k++) s += qm[i*4+k] * Minv[k*4+j];
                if (j < 3) { d_R[i*3+j] = s; d_Rc[i*3+j] = s; }
                else       { d_t[i] = s; d_tc[i] = s; }
            }
        }
        d_lam = 0.01f;
        d_sel = 0;
    }

    BilinSetup s = bilin_setup(pts2d[2*n] * SRINV, pts2d[2*n+1] * SRINV);
    const uint2* img = reinterpret_cast<const uint2*>(d_img0B);
    uint2* dst = reinterpret_cast<uint2*>(d_feat0B) + (size_t)n * C4;

    uint2 a00 = img[(size_t)s.b00*C4 + lane];
    uint2 a10 = img[(size_t)s.b10*C4 + lane];
    uint2 a01 = img[(size_t)s.b01*C4 + lane];
    uint2 a11 = img[(size_t)s.b11*C4 + lane];
#pragma unroll
    for (int j = 0; j < 8; j++) {
        uint2 n00, n10, n01, n11;
        if (j < 7) {
            int c = lane + 32*(j+1);
            n00 = img[(size_t)s.b00*C4 + c];
            n10 = img[(size_t)s.b10*C4 + c];
            n01 = img[(size_t)s.b01*C4 + c];
            n11 = img[(size_t)s.b11*C4 + c];
        }
        float f00[4], f10[4], f01[4], f11[4], o[4];
        unpack_b4(a00, f00); unpack_b4(a10, f10);
        unpack_b4(a01, f01); unpack_b4(a11, f11);
#pragma unroll
        for (int k = 0; k < 4; k++)
            o[k] = bil(f00[k], f10[k], f01[k], f11[k], s);
        dst[lane + 32*j] = pack_b4(o);
        if (j < 7) { a00 = n00; a10 = n10; a01 = n01; a11 = n11; }
    }
}

// ---------------- projection helper ----------------
__device__ __forceinline__ void project_pt(int n, const float* R, const float* t,
                                           const float* __restrict__ Km,
                                           float& px, float& py, float& pz,
                                           float& p2x, float& p2y) {
    float X = d_pts3d0[3*n], Y = d_pts3d0[3*n+1], Z = d_pts3d0[3*n+2];
    px = R[0]*X + R[1]*Y + R[2]*Z + t[0];
    py = R[3]*X + R[4]*Y + R[5]*Z + t[1];
    pz = R[6]*X + R[7]*Y + R[8]*Z + t[2];
    float qx = Km[0]*px + Km[1]*py + Km[2]*pz;
    float qy = Km[3]*px + Km[4]*py + Km[5]*pz;
    float qz = Km[6]*px + Km[7]*py + Km[8]*pz;
    p2x = qx / qz; p2y = qy / qz;
}

// ---------------- FUSED: cost + channel sums + per-block 28-term reduce ----------------
__global__ void __launch_bounds__(256) k_cost_jac(const float* __restrict__ Km) {
    int warp = threadIdx.x >> 5;
    int lane = threadIdx.x & 31;
    int n = blockIdx.x * 8 + warp;
    int wbuf = d_sel ^ 1;
    float R[9], t[3];
#pragma unroll
    for (int i = 0; i < 9; i++) R[i] = d_Rc[i];
#pragma unroll
    for (int i = 0; i < 3; i++) t[i] = d_tc[i];
    float px, py, pz, p2x, p2y;
    project_pt(n, R, t, Km, px, py, pz, p2x, p2y);
    float ix = fminf(fmaxf(p2x * SRINV, 0.f), (float)(WW-1));
    float iy = fminf(fmaxf(p2y * SRINV, 0.f), (float)(HH-1));
    BilinSetup s = bilin_setup(ix, iy);
    // gradient weights in half2 (carry fp8 un-scale)
    __half2 hw00 = __float2half2_rn(s.w00 * GSCALE_INV);
    __half2 hw10 = __float2half2_rn(s.w10 * GSCALE_INV);
    __half2 hw01 = __float2half2_rn(s.w01 * GSCALE_INV);
    __half2 hw11 = __float2half2_rn(s.w11 * GSCALE_INV);
    // image weights in bf16x2
    __nv_bfloat162 bw00 = __float2bfloat162_rn(s.w00);
    __nv_bfloat162 bw10 = __float2bfloat162_rn(s.w10);
    __nv_bfloat162 bw01 = __float2bfloat162_rn(s.w01);
    __nv_bfloat162 bw11 = __float2bfloat162_rn(s.w11);

    const uint4* IG = d_ig;
    const uint2* F0 = reinterpret_cast<const uint2*>(d_feat0B) + (size_t)n * C4;

    float cst = 0.f, sx = 0.f, sy = 0.f, sxx = 0.f, sxy = 0.f, syy = 0.f;

    uint4 a00 = IG[(size_t)s.b00*C4 + lane];
    uint4 a10 = IG[(size_t)s.b10*C4 + lane];
    uint4 a01 = IG[(size_t)s.b01*C4 + lane];
    uint4 a11 = IG[(size_t)s.b11*C4 + lane];
    uint2 af0 = F0[lane];
#pragma unroll
    for (int j = 0; j < 8; j++) {
        uint4 n00, n10, n01, n11; uint2 nf0;
        if (j < 7) {
            int c = lane + 32*(j+1);
            n00 = IG[(size_t)s.b00*C4 + c];
            n10 = IG[(size_t)s.b10*C4 + c];
            n01 = IG[(size_t)s.b01*C4 + c];
            n11 = IG[(size_t)s.b11*C4 + c];
            nf0 = F0[c];
        }

        // image + feat0 path in bf16x2 SIMD; error converted to fp32
        __nv_bfloat162 f1l = __hfma2(as_bf2(a11.x), bw11,
                              __hfma2(as_bf2(a01.x), bw01,
                               __hfma2(as_bf2(a10.x), bw10,
                                __hmul2(as_bf2(a00.x), bw00))));
        __nv_bfloat162 f1h = __hfma2(as_bf2(a11.y), bw11,
                              __hfma2(as_bf2(a01.y), bw01,
                               __hfma2(as_bf2(a10.y), bw10,
                                __hmul2(as_bf2(a00.y), bw00))));
        __nv_bfloat162 el2 = __hsub2(f1l, as_bf2(af0.x));
        __nv_bfloat162 eh2 = __hsub2(f1h, as_bf2(af0.y));
        float2 elf = __bfloat1622float2(el2);
        float2 ehf = __bfloat1622float2(eh2);
        float ev[4] = { elf.x, elf.y, ehf.x, ehf.y };

        // gradient path in half2 SIMD
        __half2 gx00l, gx00h, gy00l, gy00h;
        __half2 gx10l, gx10h, gy10l, gy10h;
        __half2 gx01l, gx01h, gy01l, gy01h;
        __half2 gx11l, gx11h, gy11l, gy11h;
        unpack_f8x4_h2(a00.z, gx00l, gx00h); unpack_f8x4_h2(a00.w, gy00l, gy00h);
        unpack_f8x4_h2(a10.z, gx10l, gx10h); unpack_f8x4_h2(a10.w, gy10l, gy10h);
        unpack_f8x4_h2(a01.z, gx01l, gx01h); unpack_f8x4_h2(a01.w, gy01l, gy01h);
        unpack_f8x4_h2(a11.z, gx11l, gx11h); unpack_f8x4_h2(a11.w, gy11l, gy11h);

        __half2 jxl = __hfma2(gx11l, hw11, __hfma2(gx01l, hw01, __hfma2(gx10l, hw10, __hmul2(gx00l, hw00))));
        __half2 jxh = __hfma2(gx11h, hw11, __hfma2(gx01h, hw01, __hfma2(gx10h, hw10, __hmul2(gx00h, hw00))));
        __half2 jyl = __hfma2(gy11l, hw11, __hfma2(gy01l, hw01, __hfma2(gy10l, hw10, __hmul2(gy00l, hw00))));
        __half2 jyh = __hfma2(gy11h, hw11, __hfma2(gy01h, hw01, __hfma2(gy10h, hw10, __hmul2(gy00h, hw00))));
        float2 jxlf = __half22float2(jxl), jxhf = __half22float2(jxh);
        float2 jylf = __half22float2(jyl), jyhf = __half22float2(jyh);
        float jxv[4] = { jxlf.x, jxlf.y, jxhf.x, jxhf.y };
        float jyv[4] = { jylf.x, jylf.y, jyhf.x, jyhf.y };

#pragma unroll
        for (int k = 0; k < 4; k++) {
            float e  = ev[k];
            float jx = jxv[k], jy = jyv[k];
            cst += e*e;
            sx += jx*e; sy += jy*e;
            sxx += jx*jx; sxy += jx*jy; syy += jy*jy;
        }
        if (j < 7) { a00 = n00; a10 = n10; a01 = n01; a11 = n11; af0 = nf0; }
    }

#pragma unroll
    for (int off = 16; off; off >>= 1) {
        cst += __shfl_down_sync(0xffffffffu, cst, off);
        sx  += __shfl_down_sync(0xffffffffu, sx,  off);
        sy  += __shfl_down_sync(0xffffffffu, sy,  off);
        sxx += __shfl_down_sync(0xffffffffu, sxx, off);
        sxy += __shfl_down_sync(0xffffffffu, sxy, off);
        syy += __shfl_down_sync(0xffffffffu, syy, off);
    }

    __shared__ float sblk[8][28];
    if (lane == 0) {
        d_candp2[2*n]   = p2x;
        d_candp2[2*n+1] = p2y;

        float fx = Km[0], fy = Km[4];
        float invz = 1.f / pz;
        float sc = invz * SRINV;
        float a00f = fx * sc, a02f = -fx * px * invz * sc;
        float a11f = fy * sc, a12f = -fy * py * invz * sc;
        float A0[6], A1[6];
        A0[0] = a00f; A0[1] = 0.f; A0[2] = a02f;
        A1[0] = 0.f; A1[1] = a11f; A1[2] = a12f;
        A0[3] = a02f*py;
        A0[4] = a00f*pz - a02f*px;
        A0[5] = -a00f*py;
        A1[3] = -(a11f*pz - a12f*py);
        A1[4] = a12f*px;
        A1[5] = a11f*px;

        sblk[warp][0] = cst;
#pragma unroll
        for (int k = 0; k < 6; k++)
            sblk[warp][1+k] = sx*A0[k] + sy*A1[k];
        int idx = 7;
#pragma unroll
        for (int k = 0; k < 6; k++)
#pragma unroll
            for (int l = k; l < 6; l++) {
                sblk[warp][idx] = sxx*A0[k]*A0[l] + sxy*(A0[k]*A1[l] + A1[k]*A0[l]) + syy*A1[k]*A1[l];
                idx++;
            }
    }
    __syncthreads();
    int tid = threadIdx.x;
    if (tid < 28) {
        float v = 0.f;
#pragma unroll
        for (int w = 0; w < 8; w++) v += sblk[w][tid];
        d_bpart[wbuf][blockIdx.x*28 + tid] = v;
    }
}

// ---------------- FUSED: reduce blocks + accept/reject + copy + LM solve ----------------
__global__ void __launch_bounds__(256) k_update(int mode, float* __restrict__ out) {
    int tid = threadIdx.x;
    int cand = d_sel ^ 1;
    const float* B = d_bpart[cand];

    __shared__ float sred[28][8];
    __shared__ float tot[28];
    if (tid < 224) {
        int comp = tid >> 3, part = tid & 7;
        float v = 0.f;
        int base = part * 64;
        for (int b = 0; b < 64; b++) v += B[(base + b)*28 + comp];
        sred[comp][part] = v;
    }
    __syncthreads();
    if (tid < 28) {
        float v = 0.f;
#pragma unroll
        for (int p = 0; p < 8; p++) v += sred[tid][p];
        tot[tid] = v;
    }
    __syncthreads();

    __shared__ int s_acc;
    if (tid == 0) {
        float newc = tot[0] / (float)NP;
        int a;
        if (mode == 0) {
            d_prev = newc;
            d_sel = 1;
            a = 1;
        } else {
            a = (newc <= d_prev) ? 1 : 0;
            if (a) {
#pragma unroll
                for (int i = 0; i < 9; i++) d_R[i] = d_Rc[i];
#pragma unroll
                for (int i = 0; i < 3; i++) d_t[i] = d_tc[i];
                d_prev = newc;
                d_sel ^= 1;
            }
            float l = d_lam * (a ? 0.1f : 10.f);
            d_lam = fminf(fmaxf(l, 1e-6f), 100.f);
        }
        if (a) {
#pragma unroll
            for (int k = 0; k < 6; k++) d_gv[k] = tot[1+k];
            int idx = 7;
            for (int k = 0; k < 6; k++)
                for (int l = k; l < 6; l++) {
                    d_Hm[k*6+l] = tot[idx];
                    d_Hm[l*6+k] = tot[idx];
                    idx++;
                }
        }
        s_acc = a;
    }
    __syncthreads();
    if (s_acc) {
        const float2* src = reinterpret_cast<const float2*>(d_candp2);
        float2* dst = reinterpret_cast<float2*>(out);
        for (int n = tid; n < NP; n += 256) dst[n] = src[n];
    }
    if (tid != 0) return;

    // ---- fp32 LM solve (single thread) ----
    float Hd[6][7];
    float lam = d_lam;
    for (int k = 0; k < 6; k++) {
        for (int l = 0; l < 6; l++) Hd[k][l] = d_Hm[k*6+l];
        Hd[k][k] += (d_Hm[k*6+k] + 1e-9f) * lam;
        Hd[k][6] = -d_gv[k];
    }
    for (int col = 0; col < 6; col++) {
        int piv = col; float best = fabsf(Hd[col][col]);
        for (int r = col+1; r < 6; r++) if (fabsf(Hd[r][col]) > best) { best = fabsf(Hd[r][col]); piv = r; }
        if (piv != col) for (int j = 0; j < 7; j++) { float tmp = Hd[col][j]; Hd[col][j] = Hd[piv][j]; Hd[piv][j] = tmp; }
        float ip = 1.0f / Hd[col][col];
        for (int r = col+1; r < 6; r++) {
            float f = Hd[r][col] * ip;
            for (int j = col; j < 7; j++) Hd[r][j] -= f * Hd[col][j];
        }
    }
    float delta[6];
    for (int r = 5; r >= 0; r--) {
        float sv = Hd[r][6];
        for (int j = r+1; j < 6; j++) sv -= Hd[r][j] * delta[j];
        delta[r] = sv / Hd[r][r];
    }
    float w0 = delta[3], w1 = delta[4], w2 = delta[5];
    float th2 = w0*w0 + w1*w1 + w2*w2;
    float th = sqrtf(fmaxf(th2, 1e-24f));
    float Ac = (th2 < 1e-16f) ? 1.0f : sinf(th) / th;
    float Bc = (th2 < 1e-16f) ? 0.5f : (1.0f - cosf(th)) / fmaxf(th2, 1e-24f);
    float dr[3][3];
    dr[0][0] = 1.0f + Bc*(w0*w0 - th2);
    dr[0][1] = -Ac*w2 + Bc*w0*w1;
    dr[0][2] =  Ac*w1 + Bc*w0*w2;
    dr[1][0] =  Ac*w2 + Bc*w1*w0;
    dr[1][1] = 1.0f + Bc*(w1*w1 - th2);
    dr[1][2] = -Ac*w0 + Bc*w1*w2;
    dr[2][0] = -Ac*w1 + Bc*w2*w0;
    dr[2][1] =  Ac*w0 + Bc*w2*w1;
    dr[2][2] = 1.0f + Bc*(w2*w2 - th2);
    for (int i = 0; i < 3; i++) {
        for (int j = 0; j < 3; j++) {
            float sv = 0.0f;
            for (int k = 0; k < 3; k++) sv += dr[i][k] * d_R[k*3+j];
            d_Rc[i*3+j] = sv;
        }
        float sv = delta[i];
        for (int k = 0; k < 3; k++) sv += dr[i][k] * d_t[k];
        d_tc[i] = sv;
    }
}

// ---------------- launch ----------------
extern "C" void kernel_launch(void* const* d_in, const int* in_sizes, int n_in,
                              void* d_out, int out_size) {
    const float* imgf0 = (const float*)d_in[0];
    const float* imgf1 = (const float*)d_in[1];
    const float* pts2d = (const float*)d_in[2];
    const float* pts3d = (const float*)d_in[3];
    const float* qm    = (const float*)d_in[4];
    const float* rm    = (const float*)d_in[5];
    const float* Km    = (const float*)d_in[6];
    float* out = (float*)d_out;

    dim3 tb(32, 8);
    k_transpose<<<dim3(HW/32, CC/32, 2), tb>>>(imgf0, imgf1);
    k_sobel<<<dim3(WW, HH), 256>>>();
    k_feat0<<<NP/8, 256>>>(pts2d, pts3d, rm, qm);

    k_cost_jac<<<NBLK, 256>>>(Km);
    k_update<<<1, 256>>>(0, out);

    for (int it = 0; it < NITERS; it++) {
        k_cost_jac<<<NBLK, 256>>>(Km);
        k_update<<<1, 256>>>(1, out);
    }
}